// round 8
// baseline (speedup 1.0000x reference)
#include <cuda_runtime.h>
#include <cuda_bf16.h>
#include <math.h>
#include <stdint.h>

#define NN 50000
#define RR 6
#define EE 32768
#define HH 256
#define FF 16
#define NHH 8
#define HDD 32

// ---------------- scratch (device globals; no allocation) ----------------
__device__ float    g_qe  [(size_t)RR*EE*HH];
__device__ float    g_kb  [(size_t)RR*EE*HH];
__device__ float    g_vb  [(size_t)RR*EE*HH];
__device__ float    g_sc  [(size_t)RR*EE*NHH];
__device__ unsigned g_m   [(size_t)RR*NN*NHH];
__device__ float    g_den [(size_t)RR*NN*NHH];
__device__ float    g_agg [(size_t)RR*NN*HH];
__device__ float    g_rel [(size_t)RR*NN*HH];
__device__ float    g_h1  [(size_t)NN*HH];
__device__ float    g_cat [(size_t)NN*2*HH];
__device__ float    g_paths[(size_t)NN*3*HH];
__device__ float    g_stk [(size_t)NN*3*HH];
__device__ float    g_t   [(size_t)NN*3*(HH/2)];
__device__ float    g_comb[(size_t)NN*HH];

// converted weights: separate hi / lo bf16 planes, [K][N] layout (as fp32)
#define OFF_WQ   0
#define OFF_WK   393216
#define OFF_WV   811008
#define OFF_WM   1228800
#define OFF_WIR1 1622016
#define OFF_WMP  2015232
#define OFF_WA1  2211840
#define OFF_WC   2244608
#define WCVT_TOT 2375680
__device__ __nv_bfloat16 g_wh[WCVT_TOT];
__device__ __nv_bfloat16 g_wl[WCVT_TOT];

// ---------------- helpers ----------------
__device__ __forceinline__ unsigned encodeF(float f) {
    unsigned u = __float_as_uint(f);
    return (u & 0x80000000u) ? ~u : (u | 0x80000000u);
}
__device__ __forceinline__ float decodeF(unsigned u) {
    return (u & 0x80000000u) ? __uint_as_float(u & 0x7fffffffu)
                             : __uint_as_float(~u);
}
__device__ __forceinline__ float gelu_exact(float v) {
    return 0.5f * v * (1.0f + erff(v * 0.7071067811865475f));
}
__device__ __forceinline__ void f2hl(float x, unsigned short& h, unsigned short& l) {
    __nv_bfloat16 hb = __float2bfloat16(x);
    __nv_bfloat16 lb = __float2bfloat16(x - __bfloat162float(hb));
    h = __bfloat16_as_ushort(hb);
    l = __bfloat16_as_ushort(lb);
}
__device__ __forceinline__ uint32_t cvta_s(const void* p) {
    return static_cast<uint32_t>(__cvta_generic_to_shared(p));
}
__device__ __forceinline__ void cp16(uint32_t dst, const void* src) {
    asm volatile("cp.async.cg.shared.global [%0], [%1], 16;"
                 :: "r"(dst), "l"(src) : "memory");
}
#define CP_COMMIT() asm volatile("cp.async.commit_group;" ::: "memory")
#define CP_WAIT0()  asm volatile("cp.async.wait_group 0;" ::: "memory")

#define LDSM4(r, addr) \
    asm volatile("ldmatrix.sync.aligned.m8n8.x4.shared.b16 {%0,%1,%2,%3},[%4];" \
        : "=r"((r)[0]), "=r"((r)[1]), "=r"((r)[2]), "=r"((r)[3]) : "r"(addr))
#define LDSM4T(r, addr) \
    asm volatile("ldmatrix.sync.aligned.m8n8.x4.trans.shared.b16 {%0,%1,%2,%3},[%4];" \
        : "=r"((r)[0]), "=r"((r)[1]), "=r"((r)[2]), "=r"((r)[3]) : "r"(addr))
#define MMA16816(d, a, b) \
    asm volatile("mma.sync.aligned.m16n8k16.row.col.f32.bf16.bf16.f32 " \
        "{%0,%1,%2,%3},{%4,%5,%6,%7},{%8,%9},{%0,%1,%2,%3};" \
        : "+f"((d)[0]), "+f"((d)[1]), "+f"((d)[2]), "+f"((d)[3]) \
        : "r"((a)[0]), "r"((a)[1]), "r"((a)[2]), "r"((a)[3]), \
          "r"((b)[0]), "r"((b)[1]))

// ---------------- zero init ----------------
__global__ void zero_kernel() {
    size_t i = (size_t)blockIdx.x * blockDim.x + threadIdx.x;
    if (i < (size_t)RR * NN * HH) g_agg[i] = 0.0f;
    if (i < (size_t)RR * NN * NHH) { g_m[i] = 0u; g_den[i] = 0.0f; }
}

// ---------------- weight conversion fp32 -> hi/lo bf16 planes ----------------
__global__ void wconv_kernel(const float* __restrict__ w, int n, size_t off) {
    int i = blockIdx.x * blockDim.x + threadIdx.x;
    if (i < n) {
        unsigned short h, l;
        f2hl(w[i], h, l);
        g_wh[off + i] = __ushort_as_bfloat16(h);
        g_wl[off + i] = __ushort_as_bfloat16(l);
    }
}

// ---------------- tensor-core split-bf16 GEMM (cp.async B, split planes) ----
// C[M,Nn] = act(A[M,K] @ B[K,Nn] + bias); block tile 128x128, warp 64x32.
// ALOAD: 0 plain, 1 relstack, 2 gather-x, 3 gather-x + eattr concat (K=272),
//        4 plain + per-32col normalization by den (xPtr = den base).
// Weights in g_wh/g_wl at offset woff, [K][Nn] layout. K % 16 == 0.
#define BM 128
#define BN 128
#define A_PL (128 * 24 * 2)
#define A_BUF (2 * A_PL)
#define B_PL (16 * 136 * 2)
#define B_BUF (2 * B_PL)

template<int ALOAD, int ACT>
__global__ __launch_bounds__(256)
void gemm_tc(const float* __restrict__ A, long long aBatch, int lda,
             const int*  __restrict__ gidx, long long gBatch,
             const float* __restrict__ xPtr,
             const float* __restrict__ eattr, long long eaBatch,
             size_t woff, long long bBatch, int ldb,
             const float* __restrict__ bias, long long biasBatch,
             float* __restrict__ C, long long cBatch, int ldc,
             int M, int Nn, int K, int relM)
{
    const int z = blockIdx.z;
    const __nv_bfloat16* Bh = g_wh + woff + (size_t)z * bBatch;
    const __nv_bfloat16* Bl = g_wl + woff + (size_t)z * bBatch;
    const float* bz  = bias + (size_t)z * biasBatch;
    float*       Cz  = C + (size_t)z * cBatch;
    const float* Az  = (ALOAD == 0 || ALOAD == 1 || ALOAD == 4)
                       ? (A + (size_t)z * aBatch) : nullptr;
    const int*   gz  = (ALOAD == 2 || ALOAD == 3) ? (gidx + (size_t)z * gBatch) : nullptr;
    const float* eaz = (ALOAD == 3) ? (eattr + (size_t)z * eaBatch) : nullptr;

    const int row0 = blockIdx.y * BM;
    const int col0 = blockIdx.x * BN;

    // sA[buf][plane][128][24], sB[buf][plane][16][136]
    __shared__ __align__(16) __nv_bfloat16 sA[2][2][BM][24];
    __shared__ __align__(16) __nv_bfloat16 sB[2][2][16][136];

    const int tid  = threadIdx.x;
    const int wid  = tid >> 5;
    const int lane = tid & 31;

    // loader mapping
    const int aRow = tid >> 1;          // 0..127
    const int aK8  = (tid & 1) * 8;     // 0 or 8
    const int bK   = tid >> 4;          // 0..15
    const int bC8  = (tid & 15) * 8;    // 0..120

    const int rowIdx = row0 + aRow;
    const bool rowOK = rowIdx < M;
    int nodeIdx = 0;
    if (ALOAD == 2 || ALOAD == 3) nodeIdx = rowOK ? gz[rowIdx] : 0;

    // mma mapping
    const int warp_m = (wid & 1) * 64;
    const int warp_n = (wid >> 1) * 32;
    const int groupID = lane >> 2;
    const int tig = lane & 3;

    const int aRowL = (lane & 7) | (((lane >> 3) & 1) << 3);
    const int aKofL = ((lane >> 4) & 1) * 8;
    const int bKrowL = (lane & 7) | (((lane >> 3) & 1) << 3);
    const int bNcolL = warp_n + ((lane >> 4) & 1) * 8;

    const uint32_t aSm = cvta_s(&sA[0][0][0][0]);
    const uint32_t bSm = cvta_s(&sB[0][0][0][0]);
    const uint32_t aThr = aSm + (uint32_t)(((warp_m + aRowL) * 24 + aKofL) * 2);
    const uint32_t bThr = bSm + (uint32_t)((bKrowL * 136 + bNcolL) * 2);

    float acc[4][4][4];
#pragma unroll
    for (int mi = 0; mi < 4; mi++)
#pragma unroll
        for (int nj = 0; nj < 4; nj++)
#pragma unroll
            for (int r = 0; r < 4; r++) acc[mi][nj][r] = 0.0f;

    float4 av0, av1;

    auto issueB = [&](int ktile, int buf) {
        const int krow = ktile * 16 + bK;
        const __nv_bfloat16* sh = Bh + (size_t)krow * ldb + col0 + bC8;
        const __nv_bfloat16* sl = Bl + (size_t)krow * ldb + col0 + bC8;
        const uint32_t dh = bSm + (uint32_t)(buf * B_BUF + (bK * 136 + bC8) * 2);
        cp16(dh, sh);
        cp16(dh + B_PL, sl);
        CP_COMMIT();
    };

    auto loadA = [&](int k0) {
        av0 = make_float4(0.f, 0.f, 0.f, 0.f);
        av1 = av0;
        const int kk = k0 + aK8;
        if (rowOK) {
            const float* p;
            if (ALOAD == 0 || ALOAD == 4) p = Az + (size_t)rowIdx * lda + kk;
            else if (ALOAD == 1) {
                const int rel = kk >> 8, cc = kk & 255;
                p = Az + ((size_t)rel * relM + rowIdx) * 256 + cc;
            } else if (ALOAD == 2) p = xPtr + (size_t)nodeIdx * 256 + kk;
            else p = (kk < 256) ? (xPtr + (size_t)nodeIdx * 256 + kk)
                                : (eaz + (size_t)rowIdx * FF + (kk - 256));
            av0 = *reinterpret_cast<const float4*>(p);
            av1 = *reinterpret_cast<const float4*>(p + 4);
            if (ALOAD == 4) {
                const float d = xPtr[((size_t)z * NN + rowIdx) * NHH + (kk >> 5)];
                const float s = 1.0f / (d + 1e-16f);
                av0.x *= s; av0.y *= s; av0.z *= s; av0.w *= s;
                av1.x *= s; av1.y *= s; av1.z *= s; av1.w *= s;
            }
        }
    };

    auto storeA = [&](int buf) {
        float af[8] = {av0.x, av0.y, av0.z, av0.w, av1.x, av1.y, av1.z, av1.w};
        unsigned short h[8], l[8];
#pragma unroll
        for (int i = 0; i < 8; i++) f2hl(af[i], h[i], l[i]);
        uint4 hu, lu;
        hu.x = (uint32_t)h[0] | ((uint32_t)h[1] << 16);
        hu.y = (uint32_t)h[2] | ((uint32_t)h[3] << 16);
        hu.z = (uint32_t)h[4] | ((uint32_t)h[5] << 16);
        hu.w = (uint32_t)h[6] | ((uint32_t)h[7] << 16);
        lu.x = (uint32_t)l[0] | ((uint32_t)l[1] << 16);
        lu.y = (uint32_t)l[2] | ((uint32_t)l[3] << 16);
        lu.z = (uint32_t)l[4] | ((uint32_t)l[5] << 16);
        lu.w = (uint32_t)l[6] | ((uint32_t)l[7] << 16);
        const uint32_t off = (uint32_t)((aRow * 24 + aK8) * 2);
        asm volatile("st.shared.v4.b32 [%0], {%1,%2,%3,%4};"
            :: "r"(aSm + buf * A_BUF + off), "r"(hu.x), "r"(hu.y), "r"(hu.z), "r"(hu.w)
            : "memory");
        asm volatile("st.shared.v4.b32 [%0], {%1,%2,%3,%4};"
            :: "r"(aSm + buf * A_BUF + A_PL + off), "r"(lu.x), "r"(lu.y), "r"(lu.z), "r"(lu.w)
            : "memory");
    };

    const int nt = K / 16;
    // prologue
    issueB(0, 0);
    loadA(0);
    storeA(0);
    CP_WAIT0();
    __syncthreads();

    for (int kt = 0; kt < nt; kt++) {
        const int c = kt & 1;
        if (kt + 1 < nt) {
            issueB(kt + 1, c ^ 1);
            loadA((kt + 1) * 16);
        }

        uint32_t bfr[2][4][2];
#pragma unroll
        for (int hl = 0; hl < 2; hl++) {
            const uint32_t base = bThr + (uint32_t)(c * B_BUF + hl * B_PL);
#pragma unroll
            for (int p = 0; p < 2; p++) {
                uint32_t t4[4];
                LDSM4T(t4, base + p * 32u);
                bfr[hl][2 * p][0] = t4[0];
                bfr[hl][2 * p][1] = t4[1];
                bfr[hl][2 * p + 1][0] = t4[2];
                bfr[hl][2 * p + 1][1] = t4[3];
            }
        }
#pragma unroll
        for (int mi = 0; mi < 4; mi++) {
            uint32_t ah[4], al[4];
            const uint32_t abufs = aThr + (uint32_t)(c * A_BUF + mi * 16 * 24 * 2);
            LDSM4(ah, abufs);
            LDSM4(al, abufs + A_PL);
#pragma unroll
            for (int nj = 0; nj < 4; nj++) {
                MMA16816(acc[mi][nj], ah, bfr[0][nj]);
                MMA16816(acc[mi][nj], ah, bfr[1][nj]);
                MMA16816(acc[mi][nj], al, bfr[0][nj]);
            }
        }
        if (kt + 1 < nt) storeA(c ^ 1);
        CP_WAIT0();
        __syncthreads();
    }

    // epilogue
#pragma unroll
    for (int mi = 0; mi < 4; mi++) {
#pragma unroll
        for (int half = 0; half < 2; half++) {
            const int r = row0 + warp_m + mi * 16 + groupID + half * 8;
            if (r >= M) continue;
#pragma unroll
            for (int nj = 0; nj < 4; nj++) {
                const int cc = col0 + warp_n + nj * 8 + tig * 2;
                float v0 = acc[mi][nj][half * 2 + 0] + bz[cc];
                float v1 = acc[mi][nj][half * 2 + 1] + bz[cc + 1];
                if (ACT == 1) { v0 = gelu_exact(v0); v1 = gelu_exact(v1); }
                else if (ACT == 2) { v0 = tanhf(v0); v1 = tanhf(v1); }
                float2 o; o.x = v0; o.y = v1;
                *reinterpret_cast<float2*>(&Cz[(size_t)r * ldc + cc]) = o;
            }
        }
    }
}

// ---------------- edge pass 1: scores + segment max ----------------
__global__ __launch_bounds__(256)
void scores_kernel(const float* __restrict__ qe, const float* __restrict__ kb,
                   const int* __restrict__ eidx, const float* __restrict__ prior,
                   float* __restrict__ sc, unsigned* __restrict__ mEnc)
{
    const int w    = (blockIdx.x * blockDim.x + threadIdx.x) >> 5;
    const int lane = threadIdx.x & 31;
    const int r = w >> 15;
    const int e = w & (EE - 1);
    const int dst = eidx[(size_t)r * 2 * EE + EE + e];
    const float* qrow = qe + (size_t)w * HH;
    const float* krow = kb + (size_t)w * HH;
    float s[NHH];
#pragma unroll
    for (int h = 0; h < NHH; h++) {
        float p = qrow[h * HDD + lane] * krow[h * HDD + lane];
#pragma unroll
        for (int o = 16; o; o >>= 1) p += __shfl_xor_sync(0xffffffffu, p, o);
        s[h] = p;
    }
    if (lane == 0) {
#pragma unroll
        for (int h = 0; h < NHH; h++) {
            const float val = s[h] * 0.17677669529663687f * prior[r * NHH + h];
            sc[(size_t)w * NHH + h] = val;
            atomicMax(&mEnc[((size_t)r * NN + dst) * NHH + h], encodeF(val));
        }
    }
}

// ---------------- fused edge pass 2+3: exp, denom accum, weighted-V scatter --
// agg holds UNNORMALIZED sum(ex*v); normalization deferred to Wm-GEMM loader.
__global__ __launch_bounds__(256)
void agg_kernel(const float* __restrict__ sc, const unsigned* __restrict__ mEnc,
                const float* __restrict__ vb, const int* __restrict__ eidx,
                float* __restrict__ den, float* __restrict__ agg)
{
    const int w    = (blockIdx.x * blockDim.x + threadIdx.x) >> 5;
    const int lane = threadIdx.x & 31;
    const int r = w >> 15;
    const int e = w & (EE - 1);
    const int dst = eidx[(size_t)r * 2 * EE + EE + e];
    const float* vrow = vb + (size_t)w * HH;
    float* arow = agg + ((size_t)r * NN + dst) * HH;
#pragma unroll
    for (int h = 0; h < NHH; h++) {
        const size_t nidx = ((size_t)r * NN + dst) * NHH + h;
        const float m = decodeF(mEnc[nidx]);
        const float ex = expf(sc[(size_t)w * NHH + h] - m);
        if (lane == 0) atomicAdd(&den[nidx], ex);
        atomicAdd(&arow[h * HDD + lane], ex * vrow[h * HDD + lane]);
    }
}

// ---------------- inter-relation softmax mix + meta paths ----------------
__global__ __launch_bounds__(256)
void inter_kernel(const float* __restrict__ h1, const float* __restrict__ Wir2,
                  const float* __restrict__ bir2, const float* __restrict__ rel,
                  float* __restrict__ cat, float* __restrict__ paths)
{
    const int n = blockIdx.x;
    const int tid = threadIdx.x;
    __shared__ float red[256];
    __shared__ float s_logit[RR];
    __shared__ float wsm[RR];

    const float hv = h1[(size_t)n * HH + tid];
    for (int r = 0; r < RR; r++) {
        red[tid] = hv * Wir2[tid * RR + r];
        __syncthreads();
        for (int s = 128; s > 0; s >>= 1) {
            if (tid < s) red[tid] += red[tid + s];
            __syncthreads();
        }
        if (tid == 0) s_logit[r] = red[0] + bir2[r];
        __syncthreads();
    }
    if (tid == 0) {
        float mx = s_logit[0];
        for (int r = 1; r < RR; r++) mx = fmaxf(mx, s_logit[r]);
        float sum = 0.f;
        float ex[RR];
        for (int r = 0; r < RR; r++) { ex[r] = expf(s_logit[r] - mx); sum += ex[r]; }
        for (int r = 0; r < RR; r++) wsm[r] = ex[r] / sum;
    }
    __syncthreads();

    float v[RR];
#pragma unroll
    for (int r = 0; r < RR; r++) v[r] = rel[((size_t)r * NN + n) * HH + tid];
    float inter = 0.f;
#pragma unroll
    for (int r = 0; r < RR; r++) inter += wsm[r] * v[r];
    cat[(size_t)n * 2 * HH + tid] = inter;
    paths[((size_t)n * 3 + 0) * HH + tid] = v[2] + v[3];
    paths[((size_t)n * 3 + 1) * HH + tid] = v[4] + v[0];
    paths[((size_t)n * 3 + 2) * HH + tid] = v[1] + v[5];
}

// ---------------- meta attention + layernorm ----------------
__global__ __launch_bounds__(256)
void meta_kernel(const float* __restrict__ tb, const float* __restrict__ Wa2,
                 const float* __restrict__ stk, const float* __restrict__ gm,
                 const float* __restrict__ bm, float* __restrict__ cat)
{
    const int n = blockIdx.x;
    const int tid = threadIdx.x;
    __shared__ float red[256];
    __shared__ float s_logit[3];
    __shared__ float attn[3];
    __shared__ float s_mu, s_rstd;

    for (int p = 0; p < 3; p++) {
        float pv = 0.f;
        if (tid < 128) pv = tb[(size_t)n * 384 + p * 128 + tid] * Wa2[tid];
        red[tid] = pv;
        __syncthreads();
        for (int s = 128; s > 0; s >>= 1) {
            if (tid < s) red[tid] += red[tid + s];
            __syncthreads();
        }
        if (tid == 0) s_logit[p] = red[0];
        __syncthreads();
    }
    if (tid == 0) {
        float mx = fmaxf(s_logit[0], fmaxf(s_logit[1], s_logit[2]));
        float e0 = expf(s_logit[0] - mx), e1 = expf(s_logit[1] - mx), e2 = expf(s_logit[2] - mx);
        float sum = e0 + e1 + e2;
        attn[0] = e0 / sum; attn[1] = e1 / sum; attn[2] = e2 / sum;
    }
    __syncthreads();

    float mp = attn[0] * stk[((size_t)n * 3 + 0) * HH + tid]
             + attn[1] * stk[((size_t)n * 3 + 1) * HH + tid]
             + attn[2] * stk[((size_t)n * 3 + 2) * HH + tid];

    red[tid] = mp;
    __syncthreads();
    for (int s = 128; s > 0; s >>= 1) { if (tid < s) red[tid] += red[tid + s]; __syncthreads(); }
    if (tid == 0) s_mu = red[0] / (float)HH;
    __syncthreads();
    const float d = mp - s_mu;
    red[tid] = d * d;
    __syncthreads();
    for (int s = 128; s > 0; s >>= 1) { if (tid < s) red[tid] += red[tid + s]; __syncthreads(); }
    if (tid == 0) s_rstd = rsqrtf(red[0] / (float)HH + 1e-5f);
    __syncthreads();

    cat[(size_t)n * 2 * HH + HH + tid] = d * s_rstd * gm[tid] + bm[tid];
}

// ---------------- final residual + layernorm ----------------
__global__ __launch_bounds__(256)
void out_kernel(const float* __restrict__ x, const float* __restrict__ comb,
                const float* __restrict__ g, const float* __restrict__ b,
                float* __restrict__ out)
{
    const int n = blockIdx.x;
    const int tid = threadIdx.x;
    __shared__ float red[256];
    __shared__ float s_mu, s_rstd;

    const float y = x[(size_t)n * HH + tid] + comb[(size_t)n * HH + tid];
    red[tid] = y;
    __syncthreads();
    for (int s = 128; s > 0; s >>= 1) { if (tid < s) red[tid] += red[tid + s]; __syncthreads(); }
    if (tid == 0) s_mu = red[0] / (float)HH;
    __syncthreads();
    const float d = y - s_mu;
    red[tid] = d * d;
    __syncthreads();
    for (int s = 128; s > 0; s >>= 1) { if (tid < s) red[tid] += red[tid + s]; __syncthreads(); }
    if (tid == 0) s_rstd = rsqrtf(red[0] / (float)HH + 1e-5f);
    __syncthreads();

    out[(size_t)n * HH + tid] = d * s_rstd * g[tid] + b[tid];
}

// ---------------- launch ----------------
extern "C" void kernel_launch(void* const* d_in, const int* in_sizes, int n_in,
                              void* d_out, int out_size)
{
    (void)in_sizes; (void)n_in; (void)out_size;
    const float* x     = (const float*)d_in[0];
    const int*   eidx  = (const int*)  d_in[1];
    const float* eattr = (const float*)d_in[2];
    const float* Wq    = (const float*)d_in[3];
    const float* bq    = (const float*)d_in[4];
    const float* Wk    = (const float*)d_in[5];
    const float* bk    = (const float*)d_in[6];
    const float* Wv    = (const float*)d_in[7];
    const float* bv    = (const float*)d_in[8];
    const float* prior = (const float*)d_in[9];
    const float* Wm    = (const float*)d_in[10];
    const float* bm    = (const float*)d_in[11];
    const float* Wir1  = (const float*)d_in[12];
    const float* bir1  = (const float*)d_in[13];
    const float* Wir2  = (const float*)d_in[14];
    const float* bir2  = (const float*)d_in[15];
    const float* Wmp   = (const float*)d_in[16];
    const float* bmp   = (const float*)d_in[17];
    const float* Wa1   = (const float*)d_in[18];
    const float* ba1   = (const float*)d_in[19];
    const float* Wa2   = (const float*)d_in[20];
    const float* gmeta = (const float*)d_in[21];
    const float* bmeta = (const float*)d_in[22];
    const float* Wc    = (const float*)d_in[23];
    const float* bc    = (const float*)d_in[24];
    const float* gout  = (const float*)d_in[25];
    const float* bout  = (const float*)d_in[26];
    float* out = (float*)d_out;

    float *p_qe, *p_kb, *p_vb, *p_sc, *p_den, *p_agg, *p_rel, *p_h1,
          *p_cat, *p_paths, *p_stk, *p_t, *p_comb;
    unsigned* p_m;
    cudaGetSymbolAddress((void**)&p_qe,   g_qe);
    cudaGetSymbolAddress((void**)&p_kb,   g_kb);
    cudaGetSymbolAddress((void**)&p_vb,   g_vb);
    cudaGetSymbolAddress((void**)&p_sc,   g_sc);
    cudaGetSymbolAddress((void**)&p_m,    g_m);
    cudaGetSymbolAddress((void**)&p_den,  g_den);
    cudaGetSymbolAddress((void**)&p_agg,  g_agg);
    cudaGetSymbolAddress((void**)&p_rel,  g_rel);
    cudaGetSymbolAddress((void**)&p_h1,   g_h1);
    cudaGetSymbolAddress((void**)&p_cat,  g_cat);
    cudaGetSymbolAddress((void**)&p_paths,g_paths);
    cudaGetSymbolAddress((void**)&p_stk,  g_stk);
    cudaGetSymbolAddress((void**)&p_t,    g_t);
    cudaGetSymbolAddress((void**)&p_comb, g_comb);

    const dim3 blk(256);
    const int gridN = (NN + BM - 1) / BM;          // 391
    const int gridE = EE / BM;                     // 256
    const int grid3N = (3 * NN + BM - 1) / BM;     // 1172

    // zero m/den/agg
    zero_kernel<<<(RR * NN * HH + 255) / 256, blk>>>();

    // convert all weights fp32 -> hi/lo bf16 planes
    wconv_kernel<<<(RR * 65536 + 255) / 256, blk>>>(Wq,   RR * 65536, OFF_WQ);
    wconv_kernel<<<(RR * 69632 + 255) / 256, blk>>>(Wk,   RR * 69632, OFF_WK);
    wconv_kernel<<<(RR * 69632 + 255) / 256, blk>>>(Wv,   RR * 69632, OFF_WV);
    wconv_kernel<<<(RR * 65536 + 255) / 256, blk>>>(Wm,   RR * 65536, OFF_WM);
    wconv_kernel<<<(1536 * 256 + 255) / 256, blk>>>(Wir1, 1536 * 256, OFF_WIR1);
    wconv_kernel<<<(3 * 65536 + 255) / 256, blk>>>(Wmp,  3 * 65536, OFF_WMP);
    wconv_kernel<<<(256 * 128 + 255) / 256, blk>>>(Wa1,  256 * 128, OFF_WA1);
    wconv_kernel<<<(512 * 256 + 255) / 256, blk>>>(Wc,   512 * 256, OFF_WC);

    // q = x[dst] @ Wq + bq
    gemm_tc<2, 0><<<dim3(2, gridE, RR), blk>>>(
        nullptr, 0, 0, eidx + EE, (long long)2 * EE, x, nullptr, 0,
        OFF_WQ, 65536, HH, bq, HH, p_qe, (long long)EE * HH, HH,
        EE, HH, HH, 0);
    // k = [x[src] | eattr] @ Wk + bk   (K=272)
    gemm_tc<3, 0><<<dim3(2, gridE, RR), blk>>>(
        nullptr, 0, 0, eidx, (long long)2 * EE, x, eattr, (long long)EE * FF,
        OFF_WK, 69632, HH, bk, HH, p_kb, (long long)EE * HH, HH,
        EE, HH, 272, 0);
    // v
    gemm_tc<3, 0><<<dim3(2, gridE, RR), blk>>>(
        nullptr, 0, 0, eidx, (long long)2 * EE, x, eattr, (long long)EE * FF,
        OFF_WV, 69632, HH, bv, HH, p_vb, (long long)EE * HH, HH,
        EE, HH, 272, 0);

    // edge softmax: scores+max, then fused exp/denom/scatter (unnormalized)
    scores_kernel<<<RR * EE / 8, blk>>>(p_qe, p_kb, eidx, prior, p_sc, p_m);
    agg_kernel<<<RR * EE / 8, blk>>>(p_sc, p_m, p_vb, eidx, p_den, p_agg);

    // rel_out = gelu((agg/den) @ Wm + bm)  -- normalization in loader (ALOAD=4)
    gemm_tc<4, 1><<<dim3(2, gridN, RR), blk>>>(
        p_agg, (long long)NN * HH, HH, nullptr, 0, p_den, nullptr, 0,
        OFF_WM, 65536, HH, bm, HH, p_rel, (long long)NN * HH, HH,
        NN, HH, HH, 0);

    // h = gelu(all_rel @ W_ir1 + b_ir1)   (rel-stacked A loader, K=1536)
    gemm_tc<1, 1><<<dim3(2, gridN, 1), blk>>>(
        p_rel, 0, 0, nullptr, 0, nullptr, nullptr, 0,
        OFF_WIR1, 0, HH, bir1, 0, p_h1, 0, HH, NN, HH, RR * HH, NN);

    // inter softmax + mix + meta paths
    inter_kernel<<<NN, blk>>>(p_h1, Wir2, bir2, p_rel, p_cat, p_paths);

    // stacked = paths @ Wmp + bmp  (z=3, strided A/C)
    gemm_tc<0, 0><<<dim3(2, gridN, 3), blk>>>(
        p_paths, 256, 768, nullptr, 0, nullptr, nullptr, 0,
        OFF_WMP, 65536, HH, bmp, HH, p_stk, 256, 768, NN, HH, HH, 0);

    // t = tanh(stacked @ Wa1 + ba1)  viewed as [3N,256] @ [256,128]
    gemm_tc<0, 2><<<dim3(1, grid3N, 1), blk>>>(
        p_stk, 0, HH, nullptr, 0, nullptr, nullptr, 0,
        OFF_WA1, 0, 128, ba1, 0, p_t, 0, 128, 3 * NN, 128, HH, 0);

    // meta attention + LN -> cat[:,256:]
    meta_kernel<<<NN, blk>>>(p_t, Wa2, p_stk, gmeta, bmeta, p_cat);

    // combined = gelu(cat @ Wc + bc)
    gemm_tc<0, 1><<<dim3(2, gridN, 1), blk>>>(
        p_cat, 0, 2 * HH, nullptr, 0, nullptr, nullptr, 0,
        OFF_WC, 0, HH, bc, 0, p_comb, 0, HH, NN, HH, 2 * HH, 0);

    // out = LN(x + combined)
    out_kernel<<<NN, blk>>>(x, p_comb, gout, bout, out);
}